// round 1
// baseline (speedup 1.0000x reference)
#include <cuda_runtime.h>

// Problem constants (fixed shapes from the dataset)
#define NN   2000                 // nodes per graph
#define EE   32000                // edges (before self loops)
#define ET   (EE + NN)            // 34000 edges incl. self loops
#define GG   32                   // B*D graphs
#define EMBD 32                   // embedding dim
#define HH   4                    // heads
#define CC   32                   // channels per head
#define HC   128                  // H*C
#define NEG_SLOPE 0.2f

// ---- scratch (device globals: no allocation allowed) ----
__device__ float g_hl[(size_t)GG * NN * HC];    // 32.8 MB: transformed features
__device__ float g_asrc[GG * NN * HH];          // per-node src logit component
__device__ float g_adst[GG * NN * HH];          // per-node dst logit component
__device__ int   g_deg[NN];
__device__ int   g_ofs[NN + 1];
__device__ int   g_fill[NN];
__device__ int   g_csr_src[ET];                 // src node per CSR slot (by dst)

// ------------------------------------------------------------------
// CSR build (topology is shared across all 32 graphs)
// ------------------------------------------------------------------
__global__ void zero_deg_kernel() {
    int i = blockIdx.x * blockDim.x + threadIdx.x;
    if (i < NN) g_deg[i] = 0;
}

__global__ void count_kernel(const int* __restrict__ adj) {
    int e = blockIdx.x * blockDim.x + threadIdx.x;
    if (e < ET) {
        int dst = (e < EE) ? adj[EE + e] : (e - EE);   // self loop: dst = node
        atomicAdd(&g_deg[dst], 1);
    }
}

// single-block inclusive scan (N=2000 -> 2 elems/thread, 1024 threads)
__global__ void scan_kernel() {
    __shared__ int tmp[1024];
    int t = threadIdx.x;
    int i0 = 2 * t, i1 = 2 * t + 1;
    int a = (i0 < NN) ? g_deg[i0] : 0;
    int b = (i1 < NN) ? g_deg[i1] : 0;
    int s = a + b;
    tmp[t] = s;
    __syncthreads();
    for (int st = 1; st < 1024; st <<= 1) {
        int u = (t >= st) ? tmp[t - st] : 0;
        __syncthreads();
        tmp[t] += u;
        __syncthreads();
    }
    int excl = tmp[t] - s;
    if (i0 < NN) { g_ofs[i0] = excl;     g_fill[i0] = excl;     }
    if (i1 < NN) { g_ofs[i1] = excl + a; g_fill[i1] = excl + a; }
    if (t == 1023) g_ofs[NN] = tmp[1023];
}

__global__ void scatter_kernel(const int* __restrict__ adj) {
    int e = blockIdx.x * blockDim.x + threadIdx.x;
    if (e < ET) {
        int src, dst;
        if (e < EE) { src = adj[e]; dst = adj[EE + e]; }
        else        { src = dst = e - EE; }
        int pos = atomicAdd(&g_fill[dst], 1);
        g_csr_src[pos] = src;
    }
}

// ------------------------------------------------------------------
// Embedding lookup + linear (32->128) + per-head logit components.
// Block = one (g,n) row, 128 threads; thread t = output channel h*32+c.
// ------------------------------------------------------------------
__global__ void __launch_bounds__(128) embed_lin_kernel(
    const int*   __restrict__ x,
    const float* __restrict__ emb,
    const float* __restrict__ lin_w,
    const float* __restrict__ att_src,
    const float* __restrict__ att_dst)
{
    int row = blockIdx.x;                 // g*NN + n
    int t   = threadIdx.x;                // 0..127
    int tok = x[row];
    const float* er = emb + (size_t)tok * EMBD;

    float acc = 0.f;
#pragma unroll
    for (int k = 0; k < EMBD; k++)
        acc = fmaf(__ldg(er + k), __ldg(lin_w + k * HC + t), acc);

    g_hl[(size_t)row * HC + t] = acc;

    // warp (= head) reduction over the 32 channels for a_src / a_dst
    int lane = t & 31, h = t >> 5;
    float vs = acc * __ldg(att_src + t);
    float vd = acc * __ldg(att_dst + t);
#pragma unroll
    for (int o = 16; o > 0; o >>= 1) {
        vs += __shfl_xor_sync(0xffffffffu, vs, o);
        vd += __shfl_xor_sync(0xffffffffu, vd, o);
    }
    if (lane == 0) {
        g_asrc[row * HH + h] = vs;
        g_adst[row * HH + h] = vd;
    }
}

// ------------------------------------------------------------------
// GAT aggregation: block = (g,n), warp = head, lane = channel.
// Pass 1: lane-strided segment max. Pass 2: serial edges — exp-sum and
// coalesced 128B gather-accumulate of hl[src] in a single pass.
// ------------------------------------------------------------------
__global__ void __launch_bounds__(128) gat_kernel(
    const float* __restrict__ bias,
    float*       __restrict__ out)
{
    int gb = blockIdx.x;                  // g*NN + n
    int n  = gb % NN;
    int gBase = gb - n;                   // g*NN
    int t = threadIdx.x;
    int lane = t & 31, h = t >> 5;

    int beg = g_ofs[n], end = g_ofs[n + 1];
    float adst = g_adst[gb * HH + h];

    // pass 1: max logit over incoming edges (lane-strided)
    float m = -1e30f;
    for (int i = beg + lane; i < end; i += 32) {
        int s = g_csr_src[i];
        float l = g_asrc[(gBase + s) * HH + h] + adst;
        l = l > 0.f ? l : NEG_SLOPE * l;
        m = fmaxf(m, l);
    }
#pragma unroll
    for (int o = 16; o > 0; o >>= 1)
        m = fmaxf(m, __shfl_xor_sync(0xffffffffu, m, o));

    // pass 2: exp-sum + weighted gather accumulate
    float acc = 0.f, ssum = 0.f;
    size_t hlbase = (size_t)gBase * HC + h * CC + lane;
    for (int i = beg; i < end; i++) {
        int s = g_csr_src[i];                               // broadcast load
        float l = g_asrc[(gBase + s) * HH + h] + adst;      // broadcast load
        l = l > 0.f ? l : NEG_SLOPE * l;
        float ex = __expf(l - m);
        ssum += ex;
        acc = fmaf(ex, g_hl[hlbase + (size_t)s * HC], acc); // 128B coalesced
    }

    out[(size_t)gb * HC + t] = acc / ssum + __ldg(bias + t);
}

// ------------------------------------------------------------------
extern "C" void kernel_launch(void* const* d_in, const int* in_sizes, int n_in,
                              void* d_out, int out_size)
{
    const int*   x       = (const int*)  d_in[0];
    const int*   adj     = (const int*)  d_in[1];
    const float* emb     = (const float*)d_in[2];
    const float* lin_w   = (const float*)d_in[3];
    const float* att_src = (const float*)d_in[4];
    const float* att_dst = (const float*)d_in[5];
    const float* bias    = (const float*)d_in[6];
    float* out = (float*)d_out;

    zero_deg_kernel<<<(NN + 255) / 256, 256>>>();
    count_kernel  <<<(ET + 255) / 256, 256>>>(adj);
    scan_kernel   <<<1, 1024>>>();
    scatter_kernel<<<(ET + 255) / 256, 256>>>(adj);

    embed_lin_kernel<<<GG * NN, 128>>>(x, emb, lin_w, att_src, att_dst);
    gat_kernel      <<<GG * NN, 128>>>(bias, out);
}

// round 2
// speedup vs baseline: 1.3149x; 1.3149x over previous
#include <cuda_runtime.h>

// Fixed problem shapes
#define NN   2000                 // nodes per graph
#define EE   32000                // edges (before self loops)
#define ET   (EE + NN)            // 34000 edges incl. self loops
#define GG   32                   // B*D graphs
#define EMBD 32                   // embedding dim
#define HH   4                    // heads
#define CC   32                   // channels per head
#define HC   128                  // H*C
#define NEG_SLOPE 0.2f
#define CAP  192                  // smem edge-staging capacity (avg deg = 17)

// ---- scratch (device globals: no allocation allowed) ----
__device__ float g_thl[NN * HC];        // 1 MB: per-TOKEN transformed features
__device__ float g_tas[NN * HH];        // per-token src-logit component
__device__ float g_tad[NN * HH];        // per-token dst-logit component
__device__ int   g_deg[NN];
__device__ int   g_ofs[NN + 1];
__device__ int   g_fill[NN];
__device__ int   g_csr_src[ET];         // src node per CSR slot (sorted by dst)

// ------------------------------------------------------------------
// CSR build (topology shared across all 32 graphs)
// ------------------------------------------------------------------
__global__ void zero_deg_kernel() {
    int i = blockIdx.x * blockDim.x + threadIdx.x;
    if (i < NN) g_deg[i] = 0;
}

__global__ void count_kernel(const int* __restrict__ adj) {
    int e = blockIdx.x * blockDim.x + threadIdx.x;
    if (e < ET) {
        int dst = (e < EE) ? adj[EE + e] : (e - EE);   // self loop: dst = node
        atomicAdd(&g_deg[dst], 1);
    }
}

// single-block scan (N=2000 -> 2 elems/thread, 1024 threads)
__global__ void scan_kernel() {
    __shared__ int tmp[1024];
    int t = threadIdx.x;
    int i0 = 2 * t, i1 = 2 * t + 1;
    int a = (i0 < NN) ? g_deg[i0] : 0;
    int b = (i1 < NN) ? g_deg[i1] : 0;
    int s = a + b;
    tmp[t] = s;
    __syncthreads();
    for (int st = 1; st < 1024; st <<= 1) {
        int u = (t >= st) ? tmp[t - st] : 0;
        __syncthreads();
        tmp[t] += u;
        __syncthreads();
    }
    int excl = tmp[t] - s;
    if (i0 < NN) { g_ofs[i0] = excl;     g_fill[i0] = excl;     }
    if (i1 < NN) { g_ofs[i1] = excl + a; g_fill[i1] = excl + a; }
    if (t == 1023) g_ofs[NN] = tmp[1023];
}

__global__ void scatter_kernel(const int* __restrict__ adj) {
    int e = blockIdx.x * blockDim.x + threadIdx.x;
    if (e < ET) {
        int src, dst;
        if (e < EE) { src = adj[e]; dst = adj[EE + e]; }
        else        { src = dst = e - EE; }
        int pos = atomicAdd(&g_fill[dst], 1);
        g_csr_src[pos] = src;
    }
}

// ------------------------------------------------------------------
// Per-TOKEN tables: t_hl[tok] = emb[tok] @ lin_w  (32 -> 128), plus
// per-head attention logit components. Only 2000 blocks.
// ------------------------------------------------------------------
__global__ void __launch_bounds__(128) token_table_kernel(
    const float* __restrict__ emb,
    const float* __restrict__ lin_w,
    const float* __restrict__ att_src,
    const float* __restrict__ att_dst)
{
    int tok = blockIdx.x;
    int t   = threadIdx.x;                // 0..127 output channel
    const float* er = emb + (size_t)tok * EMBD;

    float acc = 0.f;
#pragma unroll
    for (int k = 0; k < EMBD; k++)
        acc = fmaf(__ldg(er + k), __ldg(lin_w + k * HC + t), acc);

    g_thl[tok * HC + t] = acc;

    int lane = t & 31, h = t >> 5;
    float vs = acc * __ldg(att_src + t);
    float vd = acc * __ldg(att_dst + t);
#pragma unroll
    for (int o = 16; o > 0; o >>= 1) {
        vs += __shfl_xor_sync(0xffffffffu, vs, o);
        vd += __shfl_xor_sync(0xffffffffu, vd, o);
    }
    if (lane == 0) {
        g_tas[tok * HH + h] = vs;
        g_tad[tok * HH + h] = vd;
    }
}

// ------------------------------------------------------------------
// GAT aggregation. Block = (g,n), 128 threads; warp = head, lane = channel.
// Stage tokens + 4-head leaky logits in smem once, per-warp max + exp in
// smem, then one unrolled gather pass over the hot 1MB token table.
// ------------------------------------------------------------------
__global__ void __launch_bounds__(128) gat_kernel(
    const int*   __restrict__ x,
    const float* __restrict__ bias,
    float*       __restrict__ out)
{
    __shared__ int   s_tok[CAP];
    __shared__ float s_lg[HH][CAP];       // logits, overwritten in place by exp

    int gb = blockIdx.x;                  // g*NN + n
    int n  = gb % NN;
    int gBase = gb - n;                   // g*NN
    int t = threadIdx.x;
    int lane = t & 31, h = t >> 5;

    int beg = g_ofs[n];
    int deg = g_ofs[n + 1] - beg;

    int tok_d = __ldg(x + gb);
    float4 ad4 = *reinterpret_cast<const float4*>(&g_tad[tok_d * HH]);

    float acc, ssum;

    if (deg <= CAP) {
        // ---- stage: token ids + leaky-relu logits for all 4 heads ----
        for (int i = t; i < deg; i += 128) {
            int s   = g_csr_src[beg + i];
            int tok = __ldg(x + gBase + s);
            s_tok[i] = tok;
            float4 as = *reinterpret_cast<const float4*>(&g_tas[tok * HH]);
            float l0 = as.x + ad4.x, l1 = as.y + ad4.y;
            float l2 = as.z + ad4.z, l3 = as.w + ad4.w;
            s_lg[0][i] = l0 > 0.f ? l0 : NEG_SLOPE * l0;
            s_lg[1][i] = l1 > 0.f ? l1 : NEG_SLOPE * l1;
            s_lg[2][i] = l2 > 0.f ? l2 : NEG_SLOPE * l2;
            s_lg[3][i] = l3 > 0.f ? l3 : NEG_SLOPE * l3;
        }
        __syncthreads();

        // ---- per-warp (= head) max ----
        float m = -1e30f;
        for (int i = lane; i < deg; i += 32) m = fmaxf(m, s_lg[h][i]);
#pragma unroll
        for (int o = 16; o > 0; o >>= 1)
            m = fmaxf(m, __shfl_xor_sync(0xffffffffu, m, o));

        // ---- exp in place + sum ----
        float ps = 0.f;
        for (int i = lane; i < deg; i += 32) {
            float e = __expf(s_lg[h][i] - m);
            s_lg[h][i] = e;
            ps += e;
        }
#pragma unroll
        for (int o = 16; o > 0; o >>= 1)
            ps += __shfl_xor_sync(0xffffffffu, ps, o);
        ssum = ps;
        __syncwarp();

        // ---- unrolled gather from the hot token table ----
        const float* hl = g_thl + h * CC + lane;
        float a0 = 0.f, a1 = 0.f, a2 = 0.f, a3 = 0.f;
        int i = 0;
        for (; i + 4 <= deg; i += 4) {
            int t0 = s_tok[i], t1 = s_tok[i + 1], t2 = s_tok[i + 2], t3 = s_tok[i + 3];
            float e0 = s_lg[h][i],     e1 = s_lg[h][i + 1];
            float e2 = s_lg[h][i + 2], e3 = s_lg[h][i + 3];
            a0 = fmaf(e0, hl[t0 * HC], a0);
            a1 = fmaf(e1, hl[t1 * HC], a1);
            a2 = fmaf(e2, hl[t2 * HC], a2);
            a3 = fmaf(e3, hl[t3 * HC], a3);
        }
        for (; i < deg; i++)
            a0 = fmaf(s_lg[h][i], hl[s_tok[i] * HC], a0);
        acc = (a0 + a1) + (a2 + a3);
    } else {
        // ---- rare fallback: global two-pass (degree > CAP) ----
        float adh = (h == 0) ? ad4.x : (h == 1) ? ad4.y : (h == 2) ? ad4.z : ad4.w;
        float m = -1e30f;
        for (int i = beg + lane; i < beg + deg; i += 32) {
            int tok = __ldg(x + gBase + g_csr_src[i]);
            float l = g_tas[tok * HH + h] + adh;
            l = l > 0.f ? l : NEG_SLOPE * l;
            m = fmaxf(m, l);
        }
#pragma unroll
        for (int o = 16; o > 0; o >>= 1)
            m = fmaxf(m, __shfl_xor_sync(0xffffffffu, m, o));

        float a0 = 0.f, ps = 0.f;
        const float* hl = g_thl + h * CC + lane;
        for (int i = beg; i < beg + deg; i++) {
            int tok = __ldg(x + gBase + g_csr_src[i]);
            float l = g_tas[tok * HH + h] + adh;
            l = l > 0.f ? l : NEG_SLOPE * l;
            float e = __expf(l - m);
            ps += e;
            a0 = fmaf(e, hl[tok * HC], a0);
        }
        acc = a0; ssum = ps;
    }

    out[(size_t)gb * HC + t] = acc / ssum + __ldg(bias + t);
}

// ------------------------------------------------------------------
extern "C" void kernel_launch(void* const* d_in, const int* in_sizes, int n_in,
                              void* d_out, int out_size)
{
    const int*   x       = (const int*)  d_in[0];
    const int*   adj     = (const int*)  d_in[1];
    const float* emb     = (const float*)d_in[2];
    const float* lin_w   = (const float*)d_in[3];
    const float* att_src = (const float*)d_in[4];
    const float* att_dst = (const float*)d_in[5];
    const float* bias    = (const float*)d_in[6];
    float* out = (float*)d_out;

    zero_deg_kernel<<<(NN + 255) / 256, 256>>>();
    count_kernel  <<<(ET + 255) / 256, 256>>>(adj);
    scan_kernel   <<<1, 1024>>>();
    scatter_kernel<<<(ET + 255) / 256, 256>>>(adj);
    token_table_kernel<<<NN, 128>>>(emb, lin_w, att_src, att_dst);
    gat_kernel<<<GG * NN, 128>>>(x, bias, out);
}

// round 3
// speedup vs baseline: 2.3095x; 1.7565x over previous
#include <cuda_runtime.h>
#include <cuda_fp16.h>

// Fixed problem shapes
#define NN   2000                 // nodes per graph
#define EE   32000                // edges (before self loops)
#define ET   (EE + NN)            // 34000 edges incl. self loops
#define GG   32                   // B*D graphs
#define EMBD 32                   // embedding dim
#define HH   4                    // heads
#define CC   32                   // channels per head
#define HC   128                  // H*C
#define NEG_SLOPE 0.2f
#define CAP  96                   // smem edge-tile capacity (avg deg = 17)
#define RPB  4                    // graph-rows per block

// ---- scratch (device globals: no allocation allowed) ----
__device__ __half2 g_thl2[NN * 64];             // 512 KB per-TOKEN features, half2, ch (2j,2j+1)
__device__ __align__(16) float g_tas[NN * HH];  // per-token src-logit component
__device__ __align__(16) float g_tad[NN * HH];  // per-token dst-logit component
__device__ int   g_deg[NN];
__device__ int   g_ofs[NN + 1];
__device__ int   g_fill[NN];
__device__ int   g_csr_src[ET];                 // src node per CSR slot (sorted by dst)

// ------------------------------------------------------------------
// Per-TOKEN tables + zero g_deg. Grid = NN blocks of 128.
// ------------------------------------------------------------------
__global__ void __launch_bounds__(128) token_table_kernel(
    const float* __restrict__ emb,
    const float* __restrict__ lin_w,
    const float* __restrict__ att_src,
    const float* __restrict__ att_dst)
{
    int tok = blockIdx.x;
    int t   = threadIdx.x;                // output channel 0..127
    const float* er = emb + (size_t)tok * EMBD;

    float acc = 0.f;
#pragma unroll
    for (int k = 0; k < EMBD; k++)
        acc = fmaf(__ldg(er + k), __ldg(lin_w + k * HC + t), acc);

    // pack fp16 pairs: even lane packs (ch t, ch t+1)
    float partner = __shfl_xor_sync(0xffffffffu, acc, 1);
    if ((t & 1) == 0)
        g_thl2[tok * 64 + (t >> 1)] = __floats2half2_rn(acc, partner);

    int lane = t & 31, h = t >> 5;
    float vs = acc * __ldg(att_src + t);
    float vd = acc * __ldg(att_dst + t);
#pragma unroll
    for (int o = 16; o > 0; o >>= 1) {
        vs += __shfl_xor_sync(0xffffffffu, vs, o);
        vd += __shfl_xor_sync(0xffffffffu, vd, o);
    }
    if (lane == 0) {
        g_tas[tok * HH + h] = vs;
        g_tad[tok * HH + h] = vd;
    }
    if (t == 0) g_deg[tok] = 0;
}

// ------------------------------------------------------------------
// CSR build (topology shared across all 32 graphs)
// ------------------------------------------------------------------
__global__ void count_kernel(const int* __restrict__ adj) {
    int e = blockIdx.x * blockDim.x + threadIdx.x;
    if (e < ET) {
        int dst = (e < EE) ? adj[EE + e] : (e - EE);   // self loop: dst = node
        atomicAdd(&g_deg[dst], 1);
    }
}

__global__ void scan_kernel() {
    __shared__ int tmp[1024];
    int t = threadIdx.x;
    int i0 = 2 * t, i1 = 2 * t + 1;
    int a = (i0 < NN) ? g_deg[i0] : 0;
    int b = (i1 < NN) ? g_deg[i1] : 0;
    int s = a + b;
    tmp[t] = s;
    __syncthreads();
    for (int st = 1; st < 1024; st <<= 1) {
        int u = (t >= st) ? tmp[t - st] : 0;
        __syncthreads();
        tmp[t] += u;
        __syncthreads();
    }
    int excl = tmp[t] - s;
    if (i0 < NN) { g_ofs[i0] = excl;     g_fill[i0] = excl;     }
    if (i1 < NN) { g_ofs[i1] = excl + a; g_fill[i1] = excl + a; }
    if (t == 1023) g_ofs[NN] = tmp[1023];
}

__global__ void scatter_kernel(const int* __restrict__ adj) {
    int e = blockIdx.x * blockDim.x + threadIdx.x;
    if (e < ET) {
        int src, dst;
        if (e < EE) { src = adj[e]; dst = adj[EE + e]; }
        else        { src = dst = e - EE; }
        int pos = atomicAdd(&g_fill[dst], 1);
        g_csr_src[pos] = src;
    }
}

// ------------------------------------------------------------------
// GAT aggregation. Block = node n × 4 graphs. 256 threads:
//   r = tid>>6 (graph-row), j = tid&63 (half2 channel pair), head = j>>4.
// No max pass (shift-invariant softmax); every lane accumulates its own
// denominator, so no reductions at all. Edge tiles of CAP in smem.
// ------------------------------------------------------------------
__global__ void __launch_bounds__(256) gat_kernel(
    const int*   __restrict__ x,
    const float* __restrict__ bias,
    float*       __restrict__ out)
{
    __shared__ int   s_tok[RPB][CAP];
    __shared__ float s_w[RPB][HH][CAP];

    int n  = blockIdx.x >> 3;                      // node (shared by 8 blocks)
    int g  = ((blockIdx.x & 7) << 2) + (threadIdx.x >> 6);  // graph for this row
    int j  = threadIdx.x & 63;                     // half2 channel index
    int r  = threadIdx.x >> 6;
    int h  = j >> 4;                               // head

    int gBase = g * NN;
    int beg = g_ofs[n];
    int deg = g_ofs[n + 1] - beg;

    int tok_d = __ldg(x + gBase + n);
    float4 ad4 = *reinterpret_cast<const float4*>(&g_tad[tok_d * HH]);

    const __half2* hp = g_thl2 + j;

    float ax = 0.f, ay = 0.f, ssum = 0.f;

    for (int tb = 0; tb < deg; tb += CAP) {
        int cnt = min(CAP, deg - tb);

        // ---- stage tile: tokens + exp(leaky(logit)) for 4 heads ----
        for (int i = j; i < cnt; i += 64) {
            int s   = g_csr_src[beg + tb + i];
            int tok = __ldg(x + gBase + s);
            s_tok[r][i] = tok;
            float4 as = *reinterpret_cast<const float4*>(&g_tas[tok * HH]);
            float l0 = as.x + ad4.x, l1 = as.y + ad4.y;
            float l2 = as.z + ad4.z, l3 = as.w + ad4.w;
            l0 = l0 > 0.f ? l0 : NEG_SLOPE * l0;
            l1 = l1 > 0.f ? l1 : NEG_SLOPE * l1;
            l2 = l2 > 0.f ? l2 : NEG_SLOPE * l2;
            l3 = l3 > 0.f ? l3 : NEG_SLOPE * l3;
            s_w[r][0][i] = __expf(l0);
            s_w[r][1][i] = __expf(l1);
            s_w[r][2][i] = __expf(l2);
            s_w[r][3][i] = __expf(l3);
        }
        __syncthreads();

        // ---- gather tile from the hot 512KB fp16 token table ----
        int i = 0;
        for (; i + 4 <= cnt; i += 4) {
            int t0 = s_tok[r][i],     t1 = s_tok[r][i + 1];
            int t2 = s_tok[r][i + 2], t3 = s_tok[r][i + 3];
            float w0 = s_w[r][h][i],     w1 = s_w[r][h][i + 1];
            float w2 = s_w[r][h][i + 2], w3 = s_w[r][h][i + 3];
            float2 f0 = __half22float2(hp[t0 * 64]);
            float2 f1 = __half22float2(hp[t1 * 64]);
            float2 f2 = __half22float2(hp[t2 * 64]);
            float2 f3 = __half22float2(hp[t3 * 64]);
            ssum += (w0 + w1) + (w2 + w3);
            ax = fmaf(w0, f0.x, ax); ay = fmaf(w0, f0.y, ay);
            ax = fmaf(w1, f1.x, ax); ay = fmaf(w1, f1.y, ay);
            ax = fmaf(w2, f2.x, ax); ay = fmaf(w2, f2.y, ay);
            ax = fmaf(w3, f3.x, ax); ay = fmaf(w3, f3.y, ay);
        }
        for (; i < cnt; i++) {
            int tk = s_tok[r][i];
            float w = s_w[r][h][i];
            float2 f = __half22float2(hp[tk * 64]);
            ssum += w;
            ax = fmaf(w, f.x, ax); ay = fmaf(w, f.y, ay);
        }
        if (tb + CAP < deg) __syncthreads();   // uniform per block (same n)
    }

    float inv = 1.f / ssum;
    float2 b2 = reinterpret_cast<const float2*>(bias)[j];
    float2* orow = reinterpret_cast<float2*>(out + (size_t)(gBase + n) * HC);
    orow[j] = make_float2(fmaf(ax, inv, b2.x), fmaf(ay, inv, b2.y));
}

// ------------------------------------------------------------------
extern "C" void kernel_launch(void* const* d_in, const int* in_sizes, int n_in,
                              void* d_out, int out_size)
{
    const int*   x       = (const int*)  d_in[0];
    const int*   adj     = (const int*)  d_in[1];
    const float* emb     = (const float*)d_in[2];
    const float* lin_w   = (const float*)d_in[3];
    const float* att_src = (const float*)d_in[4];
    const float* att_dst = (const float*)d_in[5];
    const float* bias    = (const float*)d_in[6];
    float* out = (float*)d_out;

    token_table_kernel<<<NN, 128>>>(emb, lin_w, att_src, att_dst);
    count_kernel  <<<(ET + 255) / 256, 256>>>(adj);
    scan_kernel   <<<1, 1024>>>();
    scatter_kernel<<<(ET + 255) / 256, 256>>>(adj);
    gat_kernel    <<<NN * (GG / RPB), 256>>>(x, bias, out);
}

// round 4
// speedup vs baseline: 2.4060x; 1.0418x over previous
#include <cuda_runtime.h>
#include <cuda_fp16.h>

// Fixed problem shapes
#define NN   2000                 // nodes per graph
#define EE   32000                // edges (before self loops)
#define ET   (EE + NN)            // 34000 edges incl. self loops
#define GG   32                   // B*D graphs
#define EMBD 32                   // embedding dim
#define HH   4                    // heads
#define HC   128                  // H*C
#define NEG_SLOPE 0.2f
#define CAP  96                   // smem edge-tile capacity (avg deg = 17)
#define RPB  8                    // graph-rows per block
#define LUTN 2048                 // exp LUT entries over [-16,16), step 1/64
#define LUT_SCALE 64.0f

// ---- scratch (device globals: no allocation allowed) ----
__device__ __half2 g_thl2[NN * 64];             // 512 KB per-TOKEN features (half2)
__device__ __align__(16) float g_tas[NN * HH];  // per-token src-logit component
__device__ __align__(16) float g_tad[NN * HH];  // per-token dst-logit component
__device__ int   g_ofs[NN + 1];
__device__ int   g_csr_src[ET];                 // src node per CSR slot (by dst)
__device__ float g_lut[LUTN + 1];               // exp lerp table

// ------------------------------------------------------------------
// PREP: blocks 0..249 build per-token tables (8 tokens each, 128 thr/token);
// block 250 builds the whole CSR in shared memory (count -> scan -> scatter)
// and fills the exp LUT. Runs concurrently on different SMs.
// ------------------------------------------------------------------
__global__ void __launch_bounds__(1024) prep_kernel(
    const int*   __restrict__ x,        // unused here (kept for symmetry)
    const int*   __restrict__ adj,
    const float* __restrict__ emb,
    const float* __restrict__ lin_w,
    const float* __restrict__ att_src,
    const float* __restrict__ att_dst)
{
    int tid = threadIdx.x;

    if (blockIdx.x < NN / 8) {
        // ---------------- token tables: 8 tokens per block ----------------
        int tok = blockIdx.x * 8 + (tid >> 7);
        int t   = tid & 127;              // output channel 0..127
        const float* er = emb + (size_t)tok * EMBD;

        float acc = 0.f;
#pragma unroll
        for (int k = 0; k < EMBD; k++)
            acc = fmaf(__ldg(er + k), __ldg(lin_w + k * HC + t), acc);

        float partner = __shfl_xor_sync(0xffffffffu, acc, 1);
        if ((t & 1) == 0)
            g_thl2[tok * 64 + (t >> 1)] = __floats2half2_rn(acc, partner);

        int lane = t & 31, h = t >> 5;
        float vs = acc * __ldg(att_src + t);
        float vd = acc * __ldg(att_dst + t);
#pragma unroll
        for (int o = 16; o > 0; o >>= 1) {
            vs += __shfl_xor_sync(0xffffffffu, vs, o);
            vd += __shfl_xor_sync(0xffffffffu, vd, o);
        }
        if (lane == 0) {
            g_tas[tok * HH + h] = vs;
            g_tad[tok * HH + h] = vd;
        }
    } else {
        // ---------------- CSR mega-block ----------------
        __shared__ int s_cnt[NN];
        __shared__ int s_tmp[1024];

        // exp LUT (global; gat kernel copies it to smem)
        for (int k = tid; k <= LUTN; k += 1024)
            g_lut[k] = __expf(-16.0f + (float)k * (1.0f / LUT_SCALE));

        for (int i = tid; i < NN; i += 1024) s_cnt[i] = 0;
        __syncthreads();

        // count degrees (incl. self loops)
        for (int e = tid; e < ET; e += 1024) {
            int dst = (e < EE) ? adj[EE + e] : (e - EE);
            atomicAdd(&s_cnt[dst], 1);
        }
        __syncthreads();

        // exclusive scan (2 elems/thread)
        int i0 = 2 * tid, i1 = 2 * tid + 1;
        int a = (i0 < NN) ? s_cnt[i0] : 0;
        int b = (i1 < NN) ? s_cnt[i1] : 0;
        int s = a + b;
        s_tmp[tid] = s;
        __syncthreads();
        for (int st = 1; st < 1024; st <<= 1) {
            int u = (tid >= st) ? s_tmp[tid - st] : 0;
            __syncthreads();
            s_tmp[tid] += u;
            __syncthreads();
        }
        int excl = s_tmp[tid] - s;
        if (i0 < NN) { g_ofs[i0] = excl;     s_cnt[i0] = excl;     }
        if (i1 < NN) { g_ofs[i1] = excl + a; s_cnt[i1] = excl + a; }
        if (tid == 1023) g_ofs[NN] = s_tmp[1023];
        __syncthreads();

        // scatter into CSR slots (fill counters in smem)
        for (int e = tid; e < ET; e += 1024) {
            int src, dst;
            if (e < EE) { src = adj[e]; dst = adj[EE + e]; }
            else        { src = dst = e - EE; }
            int pos = atomicAdd(&s_cnt[dst], 1);
            g_csr_src[pos] = src;
        }
    }
}

// ------------------------------------------------------------------
// GAT aggregation. Block = node n x 8 graphs, 512 threads:
//   r = tid>>6 (graph-row), j = tid&63 (half2 channel pair), head = j>>4.
// exp via smem lerp LUT (no MUFU). No max pass; every lane accumulates
// its own softmax denominator. Edge tiles of CAP in smem.
// ------------------------------------------------------------------
__global__ void __launch_bounds__(512) gat_kernel(
    const int*   __restrict__ x,
    const float* __restrict__ bias,
    float*       __restrict__ out)
{
    __shared__ float s_lut[LUTN + 1];
    __shared__ int   s_tok[RPB][CAP];
    __shared__ float s_w[RPB][HH][CAP];

    int tid = threadIdx.x;
    int n  = blockIdx.x >> 2;                       // node
    int r  = tid >> 6;                              // graph-row 0..7
    int g  = ((blockIdx.x & 3) << 3) + r;           // graph
    int j  = tid & 63;                              // half2 channel pair
    int h  = j >> 4;                                // head

    // copy LUT to smem (coalesced, L1-hot)
    for (int k = tid; k <= LUTN; k += 512) s_lut[k] = g_lut[k];

    int gBase = g * NN;
    int beg = g_ofs[n];
    int deg = g_ofs[n + 1] - beg;

    int tok_d = __ldg(x + gBase + n);
    float4 ad4 = *reinterpret_cast<const float4*>(&g_tad[tok_d * HH]);

    const __half2* hp = g_thl2 + j;
    float ax = 0.f, ay = 0.f, ssum = 0.f;

    __syncthreads();   // LUT ready

    for (int tb = 0; tb < deg; tb += CAP) {
        int cnt = min(CAP, deg - tb);

        // ---- stage tile: tokens + LUT-exp(leaky(logit)) for 4 heads ----
        for (int i = j; i < cnt; i += 64) {
            int sidx = g_csr_src[beg + tb + i];
            int tok  = __ldg(x + gBase + sidx);
            s_tok[r][i] = tok;
            float4 as = *reinterpret_cast<const float4*>(&g_tas[tok * HH]);
            float l0 = as.x + ad4.x, l1 = as.y + ad4.y;
            float l2 = as.z + ad4.z, l3 = as.w + ad4.w;
            l0 = l0 > 0.f ? l0 : NEG_SLOPE * l0;
            l1 = l1 > 0.f ? l1 : NEG_SLOPE * l1;
            l2 = l2 > 0.f ? l2 : NEG_SLOPE * l2;
            l3 = l3 > 0.f ? l3 : NEG_SLOPE * l3;
#pragma unroll
            for (int q = 0; q < 4; q++) {
                float l = (q == 0) ? l0 : (q == 1) ? l1 : (q == 2) ? l2 : l3;
                float u = fmaf(l, LUT_SCALE, 1024.0f);        // (l+16)*64
                u = fminf(fmaxf(u, 0.0f), 2047.0f);
                int   ki = (int)u;
                float fr = u - (float)ki;
                float v0 = s_lut[ki];
                s_w[r][q][i] = fmaf(fr, s_lut[ki + 1] - v0, v0);
            }
        }
        __syncthreads();

        // ---- gather tile from the hot 512KB fp16 token table ----
        int i = 0;
        for (; i + 4 <= cnt; i += 4) {
            int t0 = s_tok[r][i],     t1 = s_tok[r][i + 1];
            int t2 = s_tok[r][i + 2], t3 = s_tok[r][i + 3];
            float w0 = s_w[r][h][i],     w1 = s_w[r][h][i + 1];
            float w2 = s_w[r][h][i + 2], w3 = s_w[r][h][i + 3];
            float2 f0 = __half22float2(hp[t0 * 64]);
            float2 f1 = __half22float2(hp[t1 * 64]);
            float2 f2 = __half22float2(hp[t2 * 64]);
            float2 f3 = __half22float2(hp[t3 * 64]);
            ssum += (w0 + w1) + (w2 + w3);
            ax = fmaf(w0, f0.x, ax); ay = fmaf(w0, f0.y, ay);
            ax = fmaf(w1, f1.x, ax); ay = fmaf(w1, f1.y, ay);
            ax = fmaf(w2, f2.x, ax); ay = fmaf(w2, f2.y, ay);
            ax = fmaf(w3, f3.x, ax); ay = fmaf(w3, f3.y, ay);
        }
        for (; i < cnt; i++) {
            int tk = s_tok[r][i];
            float w = s_w[r][h][i];
            float2 f = __half22float2(hp[tk * 64]);
            ssum += w;
            ax = fmaf(w, f.x, ax); ay = fmaf(w, f.y, ay);
        }
        if (tb + CAP < deg) __syncthreads();   // uniform per block (same n)
    }

    float inv = 1.f / ssum;
    float2 b2 = reinterpret_cast<const float2*>(bias)[j];
    float2* orow = reinterpret_cast<float2*>(out + (size_t)(gBase + n) * HC);
    orow[j] = make_float2(fmaf(ax, inv, b2.x), fmaf(ay, inv, b2.y));
}

// ------------------------------------------------------------------
extern "C" void kernel_launch(void* const* d_in, const int* in_sizes, int n_in,
                              void* d_out, int out_size)
{
    const int*   x       = (const int*)  d_in[0];
    const int*   adj     = (const int*)  d_in[1];
    const float* emb     = (const float*)d_in[2];
    const float* lin_w   = (const float*)d_in[3];
    const float* att_src = (const float*)d_in[4];
    const float* att_dst = (const float*)d_in[5];
    const float* bias    = (const float*)d_in[6];
    float* out = (float*)d_out;

    prep_kernel<<<NN / 8 + 1, 1024>>>(x, adj, emb, lin_w, att_src, att_dst);
    gat_kernel <<<NN * (GG / RPB), 512>>>(x, bias, out);
}

// round 5
// speedup vs baseline: 3.6202x; 1.5046x over previous
#include <cuda_runtime.h>
#include <cuda_fp16.h>

// Fixed problem shapes
#define NN   2000                 // nodes per graph
#define EE   32000                // edges (before self loops)
#define ET   (EE + NN)            // 34000 edges incl. self loops
#define GG   32                   // B*D graphs
#define EMBD 32                   // embedding dim
#define HH   4                    // heads
#define HC   128                  // H*C
#define NEG_SLOPE 0.2f
#define CAP  64                   // smem edge-tile capacity (avg deg = 17)
#define LUTN 2048                 // exp LUT entries over [-16,16), step 1/64
#define LUT_SCALE 64.0f

// ---- scratch (device globals: no allocation allowed) ----
__device__ __half2 g_thl2[NN * 64];             // 512 KB per-TOKEN features (half2)
__device__ __align__(16) float g_tas[NN * HH];  // per-token src-logit component
__device__ __align__(16) float g_tad[NN * HH];  // per-token dst-logit component
__device__ int    g_ofs[NN + 1];
__device__ int    g_csr_src[ET];                // src node per CSR slot (by dst)
__device__ float2 g_lut2[LUTN];                 // (exp_k, exp_{k+1}) pairs

// ------------------------------------------------------------------
// PREP: blocks 0..249 build per-token tables (8 tokens each);
// block 250 builds the CSR in smem (count -> scan -> scatter) + exp LUT.
// ------------------------------------------------------------------
__global__ void __launch_bounds__(1024) prep_kernel(
    const int*   __restrict__ adj,
    const float* __restrict__ emb,
    const float* __restrict__ lin_w,
    const float* __restrict__ att_src,
    const float* __restrict__ att_dst)
{
    int tid = threadIdx.x;

    if (blockIdx.x < NN / 8) {
        // ---------------- token tables: 8 tokens per block ----------------
        int tok = blockIdx.x * 8 + (tid >> 7);
        int t   = tid & 127;              // output channel 0..127
        const float* er = emb + (size_t)tok * EMBD;

        float acc = 0.f;
#pragma unroll
        for (int k = 0; k < EMBD; k++)
            acc = fmaf(__ldg(er + k), __ldg(lin_w + k * HC + t), acc);

        float partner = __shfl_xor_sync(0xffffffffu, acc, 1);
        if ((t & 1) == 0)
            g_thl2[tok * 64 + (t >> 1)] = __floats2half2_rn(acc, partner);

        int lane = t & 31, h = t >> 5;
        float vs = acc * __ldg(att_src + t);
        float vd = acc * __ldg(att_dst + t);
#pragma unroll
        for (int o = 16; o > 0; o >>= 1) {
            vs += __shfl_xor_sync(0xffffffffu, vs, o);
            vd += __shfl_xor_sync(0xffffffffu, vd, o);
        }
        if (lane == 0) {
            g_tas[tok * HH + h] = vs;
            g_tad[tok * HH + h] = vd;
        }
    } else {
        // ---------------- CSR mega-block ----------------
        __shared__ int s_cnt[NN];
        __shared__ int s_tmp[1024];

        // exp LUT as (e_k, e_{k+1}) pairs -> one LDG.64 per lookup
        for (int k = tid; k < LUTN; k += 1024) {
            float e0 = __expf(-16.0f + (float)k       * (1.0f / LUT_SCALE));
            float e1 = __expf(-16.0f + (float)(k + 1) * (1.0f / LUT_SCALE));
            g_lut2[k] = make_float2(e0, e1);
        }

        for (int i = tid; i < NN; i += 1024) s_cnt[i] = 0;
        __syncthreads();

        for (int e = tid; e < ET; e += 1024) {
            int dst = (e < EE) ? adj[EE + e] : (e - EE);
            atomicAdd(&s_cnt[dst], 1);
        }
        __syncthreads();

        int i0 = 2 * tid, i1 = 2 * tid + 1;
        int a = (i0 < NN) ? s_cnt[i0] : 0;
        int b = (i1 < NN) ? s_cnt[i1] : 0;
        int s = a + b;
        s_tmp[tid] = s;
        __syncthreads();
        for (int st = 1; st < 1024; st <<= 1) {
            int u = (tid >= st) ? s_tmp[tid - st] : 0;
            __syncthreads();
            s_tmp[tid] += u;
            __syncthreads();
        }
        int excl = s_tmp[tid] - s;
        if (i0 < NN) { g_ofs[i0] = excl;     s_cnt[i0] = excl;     }
        if (i1 < NN) { g_ofs[i1] = excl + a; s_cnt[i1] = excl + a; }
        if (tid == 1023) g_ofs[NN] = s_tmp[1023];
        __syncthreads();

        for (int e = tid; e < ET; e += 1024) {
            int src, dst;
            if (e < EE) { src = adj[e]; dst = adj[EE + e]; }
            else        { src = dst = e - EE; }
            int pos = atomicAdd(&s_cnt[dst], 1);
            g_csr_src[pos] = src;
        }
    }
}

// ------------------------------------------------------------------
// GAT aggregation. Block = node n, ALL 32 graphs. 512 threads:
//   g = tid>>4 (graph), j = tid&15 (int4 = 8 channels), head = j>>2.
// Staging: lane j stages edges i = j, j+16, ... for its graph g
// (CSR/x loads broadcast across graphs via same-address L1 hits).
// Gather: one LDG.128 from fp16 token table per lane per edge.
// ------------------------------------------------------------------
__global__ void __launch_bounds__(512) gat_kernel(
    const int*   __restrict__ x,
    const float* __restrict__ bias,
    float*       __restrict__ out)
{
    __shared__ float4 s_w4[GG][CAP];     // per (graph, edge): 4 head weights
    __shared__ int    s_tok[GG][CAP];    // per (graph, edge): src token

    int tid = threadIdx.x;
    int n = blockIdx.x;                  // node
    int g = tid >> 4;                    // graph 0..31
    int j = tid & 15;                    // int4 (8-channel) index
    int h = j >> 2;                      // head

    int gBase = g * NN;
    int beg = g_ofs[n];
    int deg = g_ofs[n + 1] - beg;

    int tok_d = __ldg(x + gBase + n);
    float4 ad4 = *reinterpret_cast<const float4*>(&g_tad[tok_d * HH]);

    const int4* hp4 = reinterpret_cast<const int4*>(g_thl2) + j;

    float a0 = 0.f, a1 = 0.f, a2 = 0.f, a3 = 0.f;
    float a4 = 0.f, a5 = 0.f, a6 = 0.f, a7 = 0.f;
    float ssum = 0.f;

    for (int tb = 0; tb < deg; tb += CAP) {
        int cnt = min(CAP, deg - tb);

        // ---- stage: token + 4 head weights per (g, edge) ----
        for (int i = j; i < cnt; i += 16) {
            int sidx = __ldg(g_csr_src + beg + tb + i);   // same addr for all g
            int tok  = __ldg(x + gBase + sidx);
            s_tok[g][i] = tok;
            float4 as = *reinterpret_cast<const float4*>(&g_tas[tok * HH]);
            float4 w4;
#pragma unroll
            for (int q = 0; q < 4; q++) {
                float l = (q == 0) ? as.x + ad4.x : (q == 1) ? as.y + ad4.y
                        : (q == 2) ? as.z + ad4.z : as.w + ad4.w;
                l = l > 0.f ? l : NEG_SLOPE * l;
                float u = fmaf(l, LUT_SCALE, 1024.0f);    // (l+16)*64
                u = fminf(fmaxf(u, 0.0f), 2047.0f);
                int   ki = (int)u;
                float fr = u - (float)ki;
                float2 lv = __ldg(&g_lut2[ki]);
                float w = fmaf(fr, lv.y - lv.x, lv.x);
                if (q == 0) w4.x = w; else if (q == 1) w4.y = w;
                else if (q == 2) w4.z = w; else w4.w = w;
            }
            s_w4[g][i] = w4;
        }
        __syncthreads();

        // ---- gather: 8 channels per lane, LDG.128 per edge ----
        const float* wf = reinterpret_cast<const float*>(&s_w4[g][0]) + h;
        int i = 0;
        for (; i + 2 <= cnt; i += 2) {
            int t0 = s_tok[g][i], t1 = s_tok[g][i + 1];
            float w0 = wf[i * 4], w1 = wf[(i + 1) * 4];
            int4 v0 = __ldg(hp4 + t0 * 16);
            int4 v1 = __ldg(hp4 + t1 * 16);
            ssum += w0 + w1;
            const __half2* q0 = reinterpret_cast<const __half2*>(&v0);
            const __half2* q1 = reinterpret_cast<const __half2*>(&v1);
            float2 p;
            p = __half22float2(q0[0]); a0 = fmaf(w0, p.x, a0); a1 = fmaf(w0, p.y, a1);
            p = __half22float2(q0[1]); a2 = fmaf(w0, p.x, a2); a3 = fmaf(w0, p.y, a3);
            p = __half22float2(q0[2]); a4 = fmaf(w0, p.x, a4); a5 = fmaf(w0, p.y, a5);
            p = __half22float2(q0[3]); a6 = fmaf(w0, p.x, a6); a7 = fmaf(w0, p.y, a7);
            p = __half22float2(q1[0]); a0 = fmaf(w1, p.x, a0); a1 = fmaf(w1, p.y, a1);
            p = __half22float2(q1[1]); a2 = fmaf(w1, p.x, a2); a3 = fmaf(w1, p.y, a3);
            p = __half22float2(q1[2]); a4 = fmaf(w1, p.x, a4); a5 = fmaf(w1, p.y, a5);
            p = __half22float2(q1[3]); a6 = fmaf(w1, p.x, a6); a7 = fmaf(w1, p.y, a7);
        }
        if (i < cnt) {
            int t0 = s_tok[g][i];
            float w0 = wf[i * 4];
            int4 v0 = __ldg(hp4 + t0 * 16);
            ssum += w0;
            const __half2* q0 = reinterpret_cast<const __half2*>(&v0);
            float2 p;
            p = __half22float2(q0[0]); a0 = fmaf(w0, p.x, a0); a1 = fmaf(w0, p.y, a1);
            p = __half22float2(q0[1]); a2 = fmaf(w0, p.x, a2); a3 = fmaf(w0, p.y, a3);
            p = __half22float2(q0[2]); a4 = fmaf(w0, p.x, a4); a5 = fmaf(w0, p.y, a5);
            p = __half22float2(q0[3]); a6 = fmaf(w0, p.x, a6); a7 = fmaf(w0, p.y, a7);
        }
        if (tb + CAP < deg) __syncthreads();   // uniform across block (same n)
    }

    float inv = 1.f / ssum;
    const float4* b4 = reinterpret_cast<const float4*>(bias) + j * 2;
    float4 bb0 = __ldg(b4), bb1 = __ldg(b4 + 1);
    float4* orow = reinterpret_cast<float4*>(out + (size_t)(gBase + n) * HC) + j * 2;
    orow[0] = make_float4(fmaf(a0, inv, bb0.x), fmaf(a1, inv, bb0.y),
                          fmaf(a2, inv, bb0.z), fmaf(a3, inv, bb0.w));
    orow[1] = make_float4(fmaf(a4, inv, bb1.x), fmaf(a5, inv, bb1.y),
                          fmaf(a6, inv, bb1.z), fmaf(a7, inv, bb1.w));
}

// ------------------------------------------------------------------
extern "C" void kernel_launch(void* const* d_in, const int* in_sizes, int n_in,
                              void* d_out, int out_size)
{
    const int*   x       = (const int*)  d_in[0];
    const int*   adj     = (const int*)  d_in[1];
    const float* emb     = (const float*)d_in[2];
    const float* lin_w   = (const float*)d_in[3];
    const float* att_src = (const float*)d_in[4];
    const float* att_dst = (const float*)d_in[5];
    const float* bias    = (const float*)d_in[6];
    float* out = (float*)d_out;

    prep_kernel<<<NN / 8 + 1, 1024>>>(adj, emb, lin_w, att_src, att_dst);
    gat_kernel <<<NN, 512>>>(x, bias, out);
}

// round 6
// speedup vs baseline: 4.2380x; 1.1707x over previous
#include <cuda_runtime.h>
#include <cuda_fp16.h>

// Fixed problem shapes
#define NN   2000                 // nodes per graph
#define EE   32000                // edges (before self loops)
#define ET   (EE + NN)            // 34000 edges incl. self loops
#define GG   32                   // B*D graphs
#define EMBD 32                   // embedding dim
#define HH   4                    // heads
#define HC   128                  // H*C
#define NEG_SLOPE 0.2f
#define CAP  32                   // smem edge-tile capacity (avg deg = 17)
#define LUTN 2048                 // exp LUT entries over [-16,16), step 1/64
#define LUT_SCALE 64.0f
#define TOKB (NN / 8)             // 250 token blocks
#define CNTB ((ET + 1023) / 1024) // 34 count blocks

// ---- scratch (device globals: no allocation allowed) ----
__device__ __half2 g_thl2[NN * 64];             // 512 KB per-TOKEN features (half2)
__device__ __align__(16) float g_tas[NN * HH];  // per-token src-logit component
__device__ __align__(16) float g_tad[NN * HH];  // per-token dst-logit component
__device__ int    g_deg[NN];                    // zero-init; scan consumes+resets
__device__ int    g_ofs[NN + 1];
__device__ int    g_fill[NN];
__device__ int    g_csr_src[ET];                // src node per CSR slot (by dst)
__device__ float2 g_lut2[LUTN];                 // (exp_k, exp_{k+1}) pairs

// ------------------------------------------------------------------
// PREP (one kernel, fully parallel): blocks 0..249 token tables,
// blocks 250..283 degree count (global atomics), block 284 exp LUT.
// ------------------------------------------------------------------
__global__ void __launch_bounds__(1024) prep_kernel(
    const int*   __restrict__ adj,
    const float* __restrict__ emb,
    const float* __restrict__ lin_w,
    const float* __restrict__ att_src,
    const float* __restrict__ att_dst)
{
    int tid = threadIdx.x;

    if (blockIdx.x < TOKB) {
        // ---------------- token tables: 8 tokens per block ----------------
        int tok = blockIdx.x * 8 + (tid >> 7);
        int t   = tid & 127;              // output channel 0..127
        const float* er = emb + (size_t)tok * EMBD;

        float acc = 0.f;
#pragma unroll
        for (int k = 0; k < EMBD; k++)
            acc = fmaf(__ldg(er + k), __ldg(lin_w + k * HC + t), acc);

        float partner = __shfl_xor_sync(0xffffffffu, acc, 1);
        if ((t & 1) == 0)
            g_thl2[tok * 64 + (t >> 1)] = __floats2half2_rn(acc, partner);

        int lane = t & 31, h = t >> 5;
        float vs = acc * __ldg(att_src + t);
        float vd = acc * __ldg(att_dst + t);
#pragma unroll
        for (int o = 16; o > 0; o >>= 1) {
            vs += __shfl_xor_sync(0xffffffffu, vs, o);
            vd += __shfl_xor_sync(0xffffffffu, vd, o);
        }
        if (lane == 0) {
            g_tas[tok * HH + h] = vs;
            g_tad[tok * HH + h] = vd;
        }
    } else if (blockIdx.x < TOKB + CNTB) {
        // ---------------- degree count (global atomics, chip-wide) --------
        int e = (blockIdx.x - TOKB) * 1024 + tid;
        if (e < ET) {
            int dst = (e < EE) ? adj[EE + e] : (e - EE);
            atomicAdd(&g_deg[dst], 1);
        }
    } else {
        // ---------------- exp LUT -----------------------------------------
        for (int k = tid; k < LUTN; k += 1024) {
            float e0 = __expf(-16.0f + (float)k       * (1.0f / LUT_SCALE));
            float e1 = __expf(-16.0f + (float)(k + 1) * (1.0f / LUT_SCALE));
            g_lut2[k] = make_float2(e0, e1);
        }
    }
}

// ------------------------------------------------------------------
// SCAN: single block; reads degrees, RESETS g_deg to zero (so the next
// graph replay starts clean), writes exclusive offsets + fill cursors.
// ------------------------------------------------------------------
__global__ void __launch_bounds__(1024) scan_kernel() {
    __shared__ int tmp[1024];
    int t = threadIdx.x;
    int i0 = 2 * t, i1 = 2 * t + 1;
    int a = (i0 < NN) ? g_deg[i0] : 0;
    int b = (i1 < NN) ? g_deg[i1] : 0;
    if (i0 < NN) g_deg[i0] = 0;
    if (i1 < NN) g_deg[i1] = 0;
    int s = a + b;
    tmp[t] = s;
    __syncthreads();
    for (int st = 1; st < 1024; st <<= 1) {
        int u = (t >= st) ? tmp[t - st] : 0;
        __syncthreads();
        tmp[t] += u;
        __syncthreads();
    }
    int excl = tmp[t] - s;
    if (i0 < NN) { g_ofs[i0] = excl;     g_fill[i0] = excl;     }
    if (i1 < NN) { g_ofs[i1] = excl + a; g_fill[i1] = excl + a; }
    if (t == 1023) g_ofs[NN] = tmp[1023];
}

// ------------------------------------------------------------------
// SCATTER: chip-wide, global atomic fill cursors.
// ------------------------------------------------------------------
__global__ void __launch_bounds__(1024) scatter_kernel(const int* __restrict__ adj) {
    int e = blockIdx.x * 1024 + threadIdx.x;
    if (e < ET) {
        int src, dst;
        if (e < EE) { src = adj[e]; dst = adj[EE + e]; }
        else        { src = dst = e - EE; }
        int pos = atomicAdd(&g_fill[dst], 1);
        g_csr_src[pos] = src;
    }
}

// ------------------------------------------------------------------
// GAT aggregation. Block = node n, ALL 32 graphs. 512 threads:
//   g = tid>>4, j = tid&15 (int4 = 8 channels), h = j>>2.
// smem stores (token, weight) pairs per (g, head, edge) -> gather inner
// loop is 1 LDS.64 + 1 LDG.128 per edge per lane, unrolled x4.
// ------------------------------------------------------------------
__global__ void __launch_bounds__(512) gat_kernel(
    const int*   __restrict__ x,
    const float* __restrict__ bias,
    float*       __restrict__ out)
{
    __shared__ float2 s_tw[GG][HH][CAP];   // 32 KB: (tok_bits, w_h)

    int tid = threadIdx.x;
    int n = blockIdx.x;
    int g = tid >> 4;
    int j = tid & 15;
    int h = j >> 2;

    int gBase = g * NN;
    int beg = g_ofs[n];
    int deg = g_ofs[n + 1] - beg;

    int tok_d = __ldg(x + gBase + n);
    float4 ad4 = *reinterpret_cast<const float4*>(&g_tad[tok_d * HH]);

    const int4* hp4 = reinterpret_cast<const int4*>(g_thl2) + j;

    float a0 = 0.f, a1 = 0.f, a2 = 0.f, a3 = 0.f;
    float a4 = 0.f, a5 = 0.f, a6 = 0.f, a7 = 0.f;
    float ssum = 0.f;

    for (int tb = 0; tb < deg; tb += CAP) {
        int cnt = min(CAP, deg - tb);

        // ---- stage: (token, weight) per (g, head, edge) ----
        for (int i = j; i < cnt; i += 16) {
            int sidx = __ldg(g_csr_src + beg + tb + i);   // broadcast across g
            int tok  = __ldg(x + gBase + sidx);
            float tokf = __int_as_float(tok);
            float4 as = *reinterpret_cast<const float4*>(&g_tas[tok * HH]);
#pragma unroll
            for (int q = 0; q < 4; q++) {
                float l = (q == 0) ? as.x + ad4.x : (q == 1) ? as.y + ad4.y
                        : (q == 2) ? as.z + ad4.z : as.w + ad4.w;
                l = l > 0.f ? l : NEG_SLOPE * l;
                float u = fmaf(l, LUT_SCALE, 1024.0f);    // (l+16)*64
                u = fminf(fmaxf(u, 0.0f), 2047.0f);
                int   ki = (int)u;
                float fr = u - (float)ki;
                float2 lv = __ldg(&g_lut2[ki]);
                s_tw[g][q][i] = make_float2(tokf, fmaf(fr, lv.y - lv.x, lv.x));
            }
        }
        __syncthreads();

        // ---- gather: 1 LDS.64 + 1 LDG.128 per edge, x4 unrolled ----
        const float2* tw = s_tw[g][h];
        int i = 0;
        for (; i + 4 <= cnt; i += 4) {
            float2 p0 = tw[i], p1 = tw[i + 1], p2 = tw[i + 2], p3 = tw[i + 3];
            int4 v0 = __ldg(hp4 + __float_as_int(p0.x) * 16);
            int4 v1 = __ldg(hp4 + __float_as_int(p1.x) * 16);
            int4 v2 = __ldg(hp4 + __float_as_int(p2.x) * 16);
            int4 v3 = __ldg(hp4 + __float_as_int(p3.x) * 16);
            ssum += (p0.y + p1.y) + (p2.y + p3.y);
            const __half2* q0 = reinterpret_cast<const __half2*>(&v0);
            const __half2* q1 = reinterpret_cast<const __half2*>(&v1);
            const __half2* q2 = reinterpret_cast<const __half2*>(&v2);
            const __half2* q3 = reinterpret_cast<const __half2*>(&v3);
            float2 p;
            p = __half22float2(q0[0]); a0 = fmaf(p0.y, p.x, a0); a1 = fmaf(p0.y, p.y, a1);
            p = __half22float2(q0[1]); a2 = fmaf(p0.y, p.x, a2); a3 = fmaf(p0.y, p.y, a3);
            p = __half22float2(q0[2]); a4 = fmaf(p0.y, p.x, a4); a5 = fmaf(p0.y, p.y, a5);
            p = __half22float2(q0[3]); a6 = fmaf(p0.y, p.x, a6); a7 = fmaf(p0.y, p.y, a7);
            p = __half22float2(q1[0]); a0 = fmaf(p1.y, p.x, a0); a1 = fmaf(p1.y, p.y, a1);
            p = __half22float2(q1[1]); a2 = fmaf(p1.y, p.x, a2); a3 = fmaf(p1.y, p.y, a3);
            p = __half22float2(q1[2]); a4 = fmaf(p1.y, p.x, a4); a5 = fmaf(p1.y, p.y, a5);
            p = __half22float2(q1[3]); a6 = fmaf(p1.y, p.x, a6); a7 = fmaf(p1.y, p.y, a7);
            p = __half22float2(q2[0]); a0 = fmaf(p2.y, p.x, a0); a1 = fmaf(p2.y, p.y, a1);
            p = __half22float2(q2[1]); a2 = fmaf(p2.y, p.x, a2); a3 = fmaf(p2.y, p.y, a3);
            p = __half22float2(q2[2]); a4 = fmaf(p2.y, p.x, a4); a5 = fmaf(p2.y, p.y, a5);
            p = __half22float2(q2[3]); a6 = fmaf(p2.y, p.x, a6); a7 = fmaf(p2.y, p.y, a7);
            p = __half22float2(q3[0]); a0 = fmaf(p3.y, p.x, a0); a1 = fmaf(p3.y, p.y, a1);
            p = __half22float2(q3[1]); a2 = fmaf(p3.y, p.x, a2); a3 = fmaf(p3.y, p.y, a3);
            p = __half22float2(q3[2]); a4 = fmaf(p3.y, p.x, a4); a5 = fmaf(p3.y, p.y, a5);
            p = __half22float2(q3[3]); a6 = fmaf(p3.y, p.x, a6); a7 = fmaf(p3.y, p.y, a7);
        }
        for (; i < cnt; i++) {
            float2 p0 = tw[i];
            int4 v0 = __ldg(hp4 + __float_as_int(p0.x) * 16);
            ssum += p0.y;
            const __half2* q0 = reinterpret_cast<const __half2*>(&v0);
            float2 p;
            p = __half22float2(q0[0]); a0 = fmaf(p0.y, p.x, a0); a1 = fmaf(p0.y, p.y, a1);
            p = __half22float2(q0[1]); a2 = fmaf(p0.y, p.x, a2); a3 = fmaf(p0.y, p.y, a3);
            p = __half22float2(q0[2]); a4 = fmaf(p0.y, p.x, a4); a5 = fmaf(p0.y, p.y, a5);
            p = __half22float2(q0[3]); a6 = fmaf(p0.y, p.x, a6); a7 = fmaf(p0.y, p.y, a7);
        }
        if (tb + CAP < deg) __syncthreads();   // uniform across block (same n)
    }

    float inv = 1.f / ssum;
    const float4* b4 = reinterpret_cast<const float4*>(bias) + j * 2;
    float4 bb0 = __ldg(b4), bb1 = __ldg(b4 + 1);
    float4* orow = reinterpret_cast<float4*>(out + (size_t)(gBase + n) * HC) + j * 2;
    orow[0] = make_float4(fmaf(a0, inv, bb0.x), fmaf(a1, inv, bb0.y),
                          fmaf(a2, inv, bb0.z), fmaf(a3, inv, bb0.w));
    orow[1] = make_float4(fmaf(a4, inv, bb1.x), fmaf(a5, inv, bb1.y),
                          fmaf(a6, inv, bb1.z), fmaf(a7, inv, bb1.w));
}

// ------------------------------------------------------------------
extern "C" void kernel_launch(void* const* d_in, const int* in_sizes, int n_in,
                              void* d_out, int out_size)
{
    const int*   x       = (const int*)  d_in[0];
    const int*   adj     = (const int*)  d_in[1];
    const float* emb     = (const float*)d_in[2];
    const float* lin_w   = (const float*)d_in[3];
    const float* att_src = (const float*)d_in[4];
    const float* att_dst = (const float*)d_in[5];
    const float* bias    = (const float*)d_in[6];
    float* out = (float*)d_out;

    prep_kernel   <<<TOKB + CNTB + 1, 1024>>>(adj, emb, lin_w, att_src, att_dst);
    scan_kernel   <<<1, 1024>>>();
    scatter_kernel<<<CNTB, 1024>>>(adj);
    gat_kernel    <<<NN, 512>>>(x, bias, out);
}